// round 4
// baseline (speedup 1.0000x reference)
#include <cuda_runtime.h>
#include <math.h>

#define NT 96

// shared weight bank (middle stages only)
#define C2W 0
#define C2B 72
#define C3W 76
#define C3B 124
#define E1W 128
#define E1B 152
#define E2W 156
#define E2B 172
#define D1W 176
#define D1B 224
#define D2W 228
#define D2B 252
#define D3W 254
#define D3B 266
#define WTOT 268

__device__ __forceinline__ float htanh(float x) {
    float y;
    asm("tanh.approx.f32 %0, %1;" : "=f"(y) : "f"(x));
    return y;
}

// fast atan2, ~1e-6 abs err; inputs are generic quaternion components (no 0/0)
__device__ __forceinline__ float fatan2(float y, float x) {
    float ax = fabsf(x), ay = fabsf(y);
    float mn = fminf(ax, ay), mx = fmaxf(ax, ay);
    float z = __fdividef(mn, mx);
    float z2 = z * z;
    float p = -0.0117212f;
    p = fmaf(p, z2,  0.05265332f);
    p = fmaf(p, z2, -0.11643287f);
    p = fmaf(p, z2,  0.19354346f);
    p = fmaf(p, z2, -0.33262347f);
    p = fmaf(p, z2,  0.99997726f);
    float a = p * z;
    if (ay > ax) a = 1.57079632679f - a;
    if (x < 0.0f) a = 3.14159265359f - a;
    return copysignf(a, y);
}

__global__ __launch_bounds__(NT, 1)
void conv_policy_kernel(const float* __restrict__ x,
                        const float* __restrict__ c1w, const float* __restrict__ c1b,
                        const float* __restrict__ c2w, const float* __restrict__ c2b,
                        const float* __restrict__ c3w, const float* __restrict__ c3b,
                        const float* __restrict__ e1w, const float* __restrict__ e1b,
                        const float* __restrict__ e2w, const float* __restrict__ e2b,
                        const float* __restrict__ d1w, const float* __restrict__ d1b,
                        const float* __restrict__ d2w, const float* __restrict__ d2b,
                        const float* __restrict__ d3w, const float* __restrict__ d3b,
                        const float* __restrict__ d4w, const float* __restrict__ d4b,
                        float* __restrict__ out)
{
    __shared__ float W[WTOT];
    // cat: rows 0-1 = dc3 (written late), rows 2-13 = jcat.
    // columns 1..15 hold data; cols 0 and 16 are ZERO pads -> branch-free dec4.
    __shared__ float cat[14][17];
    __shared__ float fm1[6][13];
    __shared__ float fm1ds[6][5];
    __shared__ float fm2[4][3];
    __shared__ float embin[6];
    __shared__ float emb1s[4];
    __shared__ float emb2s[4];
    __shared__ float dc1[4][3];
    __shared__ float dc2[2][5];

    const int t = threadIdx.x;

    // ================= phase 0: everything independent, one barrier =========
    // x loads FIRST (jcat is needed immediately after the barrier)
    for (int idx = t; idx < 180; idx += NT) {
        int c = idx / 15, l = idx % 15;
        float v;
        if (c < 6) {
            int j = c * 15 + l;
            v = (j < 2) ? 0.0f : x[7 + j - 2];
        } else {
            int j = (c - 6) * 15 + l;
            v = (j < 2) ? 0.0f : x[101 + j - 2];
        }
        cat[2 + c][1 + l] = v;
    }
    // zero the pad columns (28 writes)
    if (t >= 64 && t < 92) {
        int r = (t - 64) >> 1, c = (t & 1) ? 16 : 0;
        cat[r][c] = 0.0f;
    }
    // psi + obsd tail (fast atan2; done long before the barrier matters)
    if (t == 95) {
        float qw = x[3], qx = x[4], qy = x[5], qz = x[6];
        embin[4] = fatan2(qz, qw) - fatan2(-qx, qy);
        embin[5] = x[100];
    }
    // conv1 weights -> registers (threads 0..77)
    float w1[36], b1 = 0.0f;
    int o1 = 0, l1 = 0;
    if (t < 78) {
        o1 = t / 13; l1 = t % 13;
        #pragma unroll
        for (int i = 0; i < 36; i++) w1[i] = c1w[o1 * 36 + i];
        b1 = c1b[o1];
    }
    // middle-stage weights -> shared bank
    #define CP(off, src, n) for (int i = t; i < (n); i += NT) W[(off) + i] = (src)[i];
    CP(C2W, c2w, 72)  CP(C2B, c2b, 4)
    CP(C3W, c3w, 48)  CP(C3B, c3b, 4)
    CP(E1W, e1w, 24)  CP(E1B, e1b, 4)
    CP(E2W, e2w, 16)  CP(E2B, e2b, 4)
    CP(D1W, d1w, 48)  CP(D1B, d1b, 4)
    CP(D2W, d2w, 24)  CP(D2B, d2b, 2)
    CP(D3W, d3w, 12)  CP(D3B, d3b, 2)
    #undef CP
    // dec4 weights -> registers (threads 0..87), needed last
    float w4[42], b4 = 0.0f;
    int o4 = 0, l4 = 0;
    if (t < 88) {
        int g = t + 2; o4 = g / 15; l4 = g % 15;
        #pragma unroll
        for (int i = 0; i < 14; i++)
            #pragma unroll
            for (int h = 0; h < 3; h++)
                w4[i * 3 + h] = d4w[i * 18 + o4 * 3 + h];
        b4 = d4b[o4];
    }
    __syncthreads();

    // ================= conv1: (12,15) k=3 -> (6,13), tanh ===================
    if (t < 78) {
        float s0 = b1, s1 = 0.0f, s2 = 0.0f;
        #pragma unroll
        for (int i = 0; i < 12; i++) {
            s0 = fmaf(w1[i * 3 + 0], cat[2 + i][1 + l1 + 0], s0);
            s1 = fmaf(w1[i * 3 + 1], cat[2 + i][1 + l1 + 1], s1);
            s2 = fmaf(w1[i * 3 + 2], cat[2 + i][1 + l1 + 2], s2);
        }
        fm1[o1][l1] = htanh(s0 + s1 + s2);
    }
    __syncthreads();

    // ================= middle: warp 0 only, syncwarp barriers ===============
    if (t < 32) {
        // adaptive avg pool 13 -> 5
        if (t < 30) {
            const int   S[5] = {0, 2, 5, 7, 10};
            const int   E[5] = {3, 6, 8, 11, 13};
            const float R[5] = {1.f/3.f, 0.25f, 1.f/3.f, 0.25f, 1.f/3.f};
            int o = t / 5, p = t % 5;
            float s = 0.0f;
            for (int l = S[p]; l < E[p]; l++) s += fm1[o][l];
            fm1ds[o][p] = s * R[p];
        }
        __syncwarp();

        // conv2: (6,5) k=3 -> (4,3), tanh
        if (t < 12) {
            int o = t / 3, l = t % 3;
            float s0 = W[C2B + o], s1 = 0.0f;
            #pragma unroll
            for (int i = 0; i < 6; i++) {
                s0 = fmaf(W[C2W + (o * 6 + i) * 3 + 0], fm1ds[i][l + 0], s0);
                s1 = fmaf(W[C2W + (o * 6 + i) * 3 + 1], fm1ds[i][l + 1], s1);
                s0 = fmaf(W[C2W + (o * 6 + i) * 3 + 2], fm1ds[i][l + 2], s0);
            }
            fm2[o][l] = htanh(s0 + s1);
        }
        __syncwarp();

        // conv3: (4,3) k=3 -> (4,1), tanh (len-1 mean = identity)
        if (t < 4) {
            float s0 = W[C3B + t], s1 = 0.0f;
            #pragma unroll
            for (int i = 0; i < 4; i++) {
                s0 = fmaf(W[C3W + (t * 4 + i) * 3 + 0], fm2[i][0], s0);
                s1 = fmaf(W[C3W + (t * 4 + i) * 3 + 1], fm2[i][1], s1);
                s0 = fmaf(W[C3W + (t * 4 + i) * 3 + 2], fm2[i][2], s0);
            }
            embin[t] = htanh(s0 + s1);
        }
        __syncwarp();

        // emb1: 1x1, 6->4, tanh
        if (t < 4) {
            float s0 = W[E1B + t], s1 = 0.0f;
            #pragma unroll
            for (int i = 0; i < 6; i += 2) {
                s0 = fmaf(W[E1W + t * 6 + i], embin[i], s0);
                s1 = fmaf(W[E1W + t * 6 + i + 1], embin[i + 1], s1);
            }
            emb1s[t] = htanh(s0 + s1);
        }
        __syncwarp();

        // emb2: 1x1, 4->4, tanh
        if (t < 4) {
            float s0 = W[E2B + t], s1 = 0.0f;
            s0 = fmaf(W[E2W + t * 4 + 0], emb1s[0], s0);
            s1 = fmaf(W[E2W + t * 4 + 1], emb1s[1], s1);
            s0 = fmaf(W[E2W + t * 4 + 2], emb1s[2], s0);
            s1 = fmaf(W[E2W + t * 4 + 3], emb1s[3], s1);
            emb2s[t] = htanh(s0 + s1);
        }
        __syncwarp();

        // dec1: convT 4->4 k=3, len 1 -> 3, tanh
        if (t < 12) {
            int o = t / 3, l = t % 3;
            float s0 = W[D1B + o], s1 = 0.0f;
            s0 = fmaf(W[D1W + (0 * 4 + o) * 3 + l], emb2s[0], s0);
            s1 = fmaf(W[D1W + (1 * 4 + o) * 3 + l], emb2s[1], s1);
            s0 = fmaf(W[D1W + (2 * 4 + o) * 3 + l], emb2s[2], s0);
            s1 = fmaf(W[D1W + (3 * 4 + o) * 3 + l], emb2s[3], s1);
            dc1[o][l] = htanh(s0 + s1);
        }
        __syncwarp();

        // dec2: convT 4->2 k=3, len 3 -> 5, tanh
        if (t < 10) {
            int o = t / 5, l = t % 5;
            float s0 = W[D2B + o], s1 = 0.0f;
            #pragma unroll
            for (int i = 0; i < 4; i++)
                #pragma unroll
                for (int h = 0; h < 3; h++) {
                    int p = l - h;
                    if (p >= 0 && p < 3) {
                        if (h & 1) s1 = fmaf(W[D2W + (i * 2 + o) * 3 + h], dc1[i][p], s1);
                        else       s0 = fmaf(W[D2W + (i * 2 + o) * 3 + h], dc1[i][p], s0);
                    }
                }
            dc2[o][l] = htanh(s0 + s1);
        }
        __syncwarp();

        // dec3 + fused upsample: convT 2->2 k=3, len 13 -> 15, tanh (approx now)
        if (t < 30) {
            const int UP[13] = {0, 0, 0, 1, 1, 1, 2, 2, 3, 3, 3, 4, 4};
            int o = t / 15, l = t % 15;
            float s0 = W[D3B + o], s1 = 0.0f;
            #pragma unroll
            for (int i = 0; i < 2; i++)
                #pragma unroll
                for (int h = 0; h < 3; h++) {
                    int p = l - h;
                    if (p >= 0 && p < 13) {
                        if (h & 1) s1 = fmaf(W[D3W + (i * 2 + o) * 3 + h], dc2[i][UP[p]], s1);
                        else       s0 = fmaf(W[D3W + (i * 2 + o) * 3 + h], dc2[i][UP[p]], s0);
                    }
                }
            cat[o][1 + l] = htanh(s0 + s1);
        }
    }
    __syncthreads();

    // ====== dec4: convT 14->6 k=3 pad=1, (14,15)->(6,15), drop 2; branch-free
    if (t < 88) {
        float s0 = b4, s1 = 0.0f, s2 = 0.0f;
        #pragma unroll
        for (int h = 0; h < 3; h++) {
            int p = l4 - h + 2;   // in [0..16], pads are zero
            #pragma unroll
            for (int i = 0; i < 14; i++) {
                float v = cat[i][p];
                if (i % 3 == 0)      s0 = fmaf(w4[i * 3 + h], v, s0);
                else if (i % 3 == 1) s1 = fmaf(w4[i * 3 + h], v, s1);
                else                 s2 = fmaf(w4[i * 3 + h], v, s2);
            }
        }
        out[t] = s0 + s1 + s2;
    }
}

extern "C" void kernel_launch(void* const* d_in, const int* in_sizes, int n_in,
                              void* d_out, int out_size) {
    (void)in_sizes; (void)n_in; (void)out_size;
    conv_policy_kernel<<<1, NT>>>(
        (const float*)d_in[0],
        (const float*)d_in[1],  (const float*)d_in[2],
        (const float*)d_in[3],  (const float*)d_in[4],
        (const float*)d_in[5],  (const float*)d_in[6],
        (const float*)d_in[7],  (const float*)d_in[8],
        (const float*)d_in[9],  (const float*)d_in[10],
        (const float*)d_in[11], (const float*)d_in[12],
        (const float*)d_in[13], (const float*)d_in[14],
        (const float*)d_in[15], (const float*)d_in[16],
        (const float*)d_in[17], (const float*)d_in[18],
        (float*)d_out);
}

// round 5
// speedup vs baseline: 1.2452x; 1.2452x over previous
#include <cuda_runtime.h>
#include <math.h>

#define NT 128

// reduced shared weight bank (stages still read from smem)
#define C3W 0
#define C3B 48
#define E1W 52
#define E1B 76
#define E2W 80
#define E2B 96
#define D1W 100
#define D1B 148
#define WTOT 152

__device__ __forceinline__ float htanh(float x) {
    float y;
    asm("tanh.approx.f32 %0, %1;" : "=f"(y) : "f"(x));
    return y;
}

// fast atan2, ~1e-6 abs err (quaternion components, no 0/0 case)
__device__ __forceinline__ float fatan2(float y, float x) {
    float ax = fabsf(x), ay = fabsf(y);
    float mn = fminf(ax, ay), mx = fmaxf(ax, ay);
    float z = __fdividef(mn, mx);
    float z2 = z * z;
    float p = -0.0117212f;
    p = fmaf(p, z2,  0.05265332f);
    p = fmaf(p, z2, -0.11643287f);
    p = fmaf(p, z2,  0.19354346f);
    p = fmaf(p, z2, -0.33262347f);
    p = fmaf(p, z2,  0.99997726f);
    float a = p * z;
    if (ay > ax) a = 1.57079632679f - a;
    if (x < 0.0f) a = 3.14159265359f - a;
    return copysignf(a, y);
}

__global__ __launch_bounds__(NT, 1)
void conv_policy_kernel(const float* __restrict__ x,
                        const float* __restrict__ c1w, const float* __restrict__ c1b,
                        const float* __restrict__ c2w, const float* __restrict__ c2b,
                        const float* __restrict__ c3w, const float* __restrict__ c3b,
                        const float* __restrict__ e1w, const float* __restrict__ e1b,
                        const float* __restrict__ e2w, const float* __restrict__ e2b,
                        const float* __restrict__ d1w, const float* __restrict__ d1b,
                        const float* __restrict__ d2w, const float* __restrict__ d2b,
                        const float* __restrict__ d3w, const float* __restrict__ d3b,
                        const float* __restrict__ d4w, const float* __restrict__ d4b,
                        float* __restrict__ out)
{
    __shared__ float W[WTOT];
    // cat rows 0-1: dc3 (written by dec3); rows 2-13: jcat. cols 0,16 = zero pad.
    __shared__ float cat[14][17];
    __shared__ float fm1[6][14];    // col 13 = pad (never summed)
    __shared__ float embin2[2];     // psi, obsd_last

    const int t = threadIdx.x;

    // ===================== phase 0: one big independent load wave ===========
    // jcat (needed first)
    for (int idx = t; idx < 180; idx += NT) {
        int c = idx / 15, l = idx % 15;
        float v;
        if (c < 6) {
            int j = c * 15 + l;
            v = (j < 2) ? 0.0f : x[7 + j - 2];
        } else {
            int j = (c - 6) * 15 + l;
            v = (j < 2) ? 0.0f : x[101 + j - 2];
        }
        cat[2 + c][1 + l] = v;
    }
    // zero pad columns of cat (28 writes, warp 2)
    if (t >= 64 && t < 92) {
        int r = (t - 64) >> 1, c = (t & 1) ? 16 : 0;
        cat[r][c] = 0.0f;
    }
    // psi + obsd tail (warp 3 idle lane)
    if (t == 127) {
        float qw = x[3], qx = x[4], qy = x[5], qz = x[6];
        embin2[0] = fatan2(qz, qw) - fatan2(-qx, qy);
        embin2[1] = x[100];
    }
    // conv1 weights -> regs (threads 0..77)
    float w1[36], b1 = 0.0f;
    int o1 = 0, l1 = 0;
    if (t < 78) {
        o1 = t / 13; l1 = t % 13;
        #pragma unroll
        for (int i = 0; i < 36; i++) w1[i] = c1w[o1 * 36 + i];
        b1 = c1b[o1];
    }
    // per-lane stage weights for warp 0 (preselected, zero-masked)
    float wc2[19];          // conv2: 18 w + bias  (lanes 0..11)
    if (t < 12) {
        int o = t / 3;
        #pragma unroll
        for (int k = 0; k < 18; k++) wc2[k] = c2w[o * 18 + k];
        wc2[18] = c2b[o];
    }
    float wd2[13];          // dec2: w_eff[i*3+p] + bias  (lanes 0..9)
    if (t < 10) {
        int o = t / 5, l = t % 5;
        #pragma unroll
        for (int i = 0; i < 4; i++)
            #pragma unroll
            for (int p = 0; p < 3; p++) {
                int h = l - p;
                wd2[i * 3 + p] = (h >= 0 && h < 3) ? d2w[(i * 2 + o) * 3 + h] : 0.0f;
            }
        wd2[12] = d2b[o];
    }
    float wd3[7];           // dec3: w_eff[i*3+h] + bias  (lanes 0..29)
    if (t < 30) {
        int o = t / 15, l = t % 15;
        #pragma unroll
        for (int i = 0; i < 2; i++)
            #pragma unroll
            for (int h = 0; h < 3; h++) {
                int p = l - h;
                wd3[i * 3 + h] = (p >= 0 && p < 13) ? d3w[(i * 2 + o) * 3 + h] : 0.0f;
            }
        wd3[6] = d3b[o];
    }
    // shared bank for the remaining tiny stages
    #define CP(off, src, n) for (int i = t; i < (n); i += NT) W[(off) + i] = (src)[i];
    CP(C3W, c3w, 48)  CP(C3B, c3b, 4)
    CP(E1W, e1w, 24)  CP(E1B, e1b, 4)
    CP(E2W, e2w, 16)  CP(E2B, e2b, 4)
    CP(D1W, d1w, 48)  CP(D1B, d1b, 4)
    #undef CP
    // dec4 weights -> regs on threads 32..119 (needed last)
    float w4[42], b4 = 0.0f;
    int o4 = 0, l4 = 0;
    if (t >= 32 && t < 120) {
        int g = (t - 32) + 2; o4 = g / 15; l4 = g % 15;
        #pragma unroll
        for (int i = 0; i < 14; i++)
            #pragma unroll
            for (int h = 0; h < 3; h++)
                w4[i * 3 + h] = d4w[i * 18 + o4 * 3 + h];
        b4 = d4b[o4];
    }
    __syncthreads();

    // ===================== conv1: (12,15) k=3 -> (6,13), tanh ===============
    if (t < 78) {
        float s0 = b1, s1 = 0.0f, s2 = 0.0f;
        #pragma unroll
        for (int i = 0; i < 12; i++) {
            s0 = fmaf(w1[i * 3 + 0], cat[2 + i][1 + l1 + 0], s0);
            s1 = fmaf(w1[i * 3 + 1], cat[2 + i][1 + l1 + 1], s1);
            s2 = fmaf(w1[i * 3 + 2], cat[2 + i][1 + l1 + 2], s2);
        }
        fm1[o1][l1] = htanh(s0 + s1 + s2);
    }
    __syncthreads();

    float partial = 0.0f;
    if (t < 32) {
        // ============ middle: warp 0, register-resident, shuffle-chained ====
        const unsigned FULL = 0xffffffffu;

        // pool 13 -> 5: value lives in lane o*5+p (lanes 0..29)
        int rr = (t < 30) ? t : 0;
        int po = rr / 5, pp = rr % 5;
        int S = (pp * 13) / 5;
        int sz4 = (((pp + 1) * 13 + 4) / 5 - S) == 4;
        float v3 = fm1[po][S + 3];
        float vp = fm1[po][S] + fm1[po][S + 1] + fm1[po][S + 2] + (sz4 ? v3 : 0.0f);
        vp *= sz4 ? 0.25f : (1.0f / 3.0f);

        // conv2: lanes 0..11 (o*3+l)
        int r2 = (t < 12) ? t : 0;
        int l2 = r2 % 3;
        float a0 = wc2[18], a1 = 0.0f;
        #pragma unroll
        for (int i = 0; i < 6; i++) {
            float v0 = __shfl_sync(FULL, vp, i * 5 + l2 + 0);
            float v1 = __shfl_sync(FULL, vp, i * 5 + l2 + 1);
            float v2 = __shfl_sync(FULL, vp, i * 5 + l2 + 2);
            a0 = fmaf(wc2[i * 3 + 0], v0, a0);
            a1 = fmaf(wc2[i * 3 + 1], v1, a1);
            a0 = fmaf(wc2[i * 3 + 2], v2, a0);
        }
        float fm2v = htanh(a0 + a1);

        // conv3: lanes 0..3 (len-1 mean = identity)
        int oc = t & 3;
        float c0 = W[C3B + oc], c1 = 0.0f;
        #pragma unroll
        for (int i = 0; i < 4; i++)
            #pragma unroll
            for (int h = 0; h < 3; h++) {
                float v = __shfl_sync(FULL, fm2v, i * 3 + h);
                float w = W[C3W + (oc * 4 + i) * 3 + h];
                if (h & 1) c1 = fmaf(w, v, c1); else c0 = fmaf(w, v, c0);
            }
        float c3v = htanh(c0 + c1);

        // emb1: lanes 0..3 (6->4)
        float e0 = W[E1B + oc], e1a = 0.0f;
        #pragma unroll
        for (int i = 0; i < 4; i++) {
            float v = __shfl_sync(FULL, c3v, i);
            if (i & 1) e1a = fmaf(W[E1W + oc * 6 + i], v, e1a);
            else       e0  = fmaf(W[E1W + oc * 6 + i], v, e0);
        }
        e0  = fmaf(W[E1W + oc * 6 + 4], embin2[0], e0);
        e1a = fmaf(W[E1W + oc * 6 + 5], embin2[1], e1a);
        float e1v = htanh(e0 + e1a);

        // emb2: lanes 0..3 (4->4)
        float f0 = W[E2B + oc], f1 = 0.0f;
        #pragma unroll
        for (int i = 0; i < 4; i++) {
            float v = __shfl_sync(FULL, e1v, i);
            if (i & 1) f1 = fmaf(W[E2W + oc * 4 + i], v, f1);
            else       f0 = fmaf(W[E2W + oc * 4 + i], v, f0);
        }
        float e2v = htanh(f0 + f1);

        // dec1: lanes 0..11 (o*3+l)
        int rd = (t < 12) ? t : 0;
        int od = rd / 3, ld = rd % 3;
        float g0 = W[D1B + od], g1 = 0.0f;
        #pragma unroll
        for (int i = 0; i < 4; i++) {
            float v = __shfl_sync(FULL, e2v, i);
            float w = W[D1W + (i * 4 + od) * 3 + ld];
            if (i & 1) g1 = fmaf(w, v, g1); else g0 = fmaf(w, v, g0);
        }
        float d1v = htanh(g0 + g1);

        // dec2: lanes 0..9 (o*5+l), weights preselected/zero-masked
        float h0 = wd2[12], h1 = 0.0f;
        #pragma unroll
        for (int i = 0; i < 4; i++)
            #pragma unroll
            for (int p = 0; p < 3; p++) {
                float v = __shfl_sync(FULL, d1v, i * 3 + p);
                if (p & 1) h1 = fmaf(wd2[i * 3 + p], v, h1);
                else       h0 = fmaf(wd2[i * 3 + p], v, h0);
            }
        float d2v = htanh(h0 + h1);

        // dec3 + fused upsample: lanes 0..29 (o*15+l) -> cat rows 0,1
        int r3 = (t < 30) ? t : 0;
        int o3 = r3 / 15, l3 = r3 % 15;
        float k0 = wd3[6], k1 = 0.0f;
        #pragma unroll
        for (int i = 0; i < 2; i++)
            #pragma unroll
            for (int h = 0; h < 3; h++) {
                int p = l3 - h;
                int pc = p < 0 ? 0 : (p > 12 ? 12 : p);
                int q = (pc * 5) / 13;                 // UP_IDX
                float v = __shfl_sync(FULL, d2v, i * 5 + q);
                if (h & 1) k1 = fmaf(wd3[i * 3 + h], v, k1);
                else       k0 = fmaf(wd3[i * 3 + h], v, k0);
            }
        if (t < 30) cat[o3][1 + l3] = htanh(k0 + k1);
    } else if (t < 120) {
        // ===== dec4 jcat partial (i=2..13), hidden under warp-0 middle ======
        float s0 = b4, s1 = 0.0f, s2 = 0.0f;
        #pragma unroll
        for (int h = 0; h < 3; h++) {
            int p = l4 - h + 2;   // [0..16], pads zero
            #pragma unroll
            for (int i = 2; i < 14; i++) {
                float v = cat[i][p];
                if (i % 3 == 0)      s0 = fmaf(w4[i * 3 + h], v, s0);
                else if (i % 3 == 1) s1 = fmaf(w4[i * 3 + h], v, s1);
                else                 s2 = fmaf(w4[i * 3 + h], v, s2);
            }
        }
        partial = s0 + s1 + s2;
    }
    __syncthreads();

    // ===================== dec4 finish: only the dc3 rows (6 FMA) ===========
    if (t >= 32 && t < 120) {
        float s = partial;
        #pragma unroll
        for (int h = 0; h < 3; h++) {
            int p = l4 - h + 2;
            s = fmaf(w4[0 * 3 + h], cat[0][p], s);
            s = fmaf(w4[1 * 3 + h], cat[1][p], s);
        }
        out[t - 32] = s;
    }
}

extern "C" void kernel_launch(void* const* d_in, const int* in_sizes, int n_in,
                              void* d_out, int out_size) {
    (void)in_sizes; (void)n_in; (void)out_size;
    conv_policy_kernel<<<1, NT>>>(
        (const float*)d_in[0],
        (const float*)d_in[1],  (const float*)d_in[2],
        (const float*)d_in[3],  (const float*)d_in[4],
        (const float*)d_in[5],  (const float*)d_in[6],
        (const float*)d_in[7],  (const float*)d_in[8],
        (const float*)d_in[9],  (const float*)d_in[10],
        (const float*)d_in[11], (const float*)d_in[12],
        (const float*)d_in[13], (const float*)d_in[14],
        (const float*)d_in[15], (const float*)d_in[16],
        (const float*)d_in[17], (const float*)d_in[18],
        (float*)d_out);
}

// round 6
// speedup vs baseline: 1.2512x; 1.0048x over previous
#include <cuda_runtime.h>
#include <math.h>

#define NT 224

// shared weight bank for tiny middle stages
#define C3W 0
#define C3B 48
#define E1W 52
#define E1B 76
#define E2W 80
#define E2B 96
#define D1W 100
#define D1B 148
#define WTOT 152

__device__ __forceinline__ float htanh(float x) {
    float y;
    asm("tanh.approx.f32 %0, %1;" : "=f"(y) : "f"(x));
    return y;
}

// fast atan2, ~1e-6 abs err (quaternion components, no 0/0 case)
__device__ __forceinline__ float fatan2(float y, float x) {
    float ax = fabsf(x), ay = fabsf(y);
    float mn = fminf(ax, ay), mx = fmaxf(ax, ay);
    float z = __fdividef(mn, mx);
    float z2 = z * z;
    float p = -0.0117212f;
    p = fmaf(p, z2,  0.05265332f);
    p = fmaf(p, z2, -0.11643287f);
    p = fmaf(p, z2,  0.19354346f);
    p = fmaf(p, z2, -0.33262347f);
    p = fmaf(p, z2,  0.99997726f);
    float a = p * z;
    if (ay > ax) a = 1.57079632679f - a;
    if (x < 0.0f) a = 3.14159265359f - a;
    return copysignf(a, y);
}

__global__ __launch_bounds__(NT, 1)
void conv_policy_kernel(const float* __restrict__ x,
                        const float* __restrict__ c1w, const float* __restrict__ c1b,
                        const float* __restrict__ c2w, const float* __restrict__ c2b,
                        const float* __restrict__ c3w, const float* __restrict__ c3b,
                        const float* __restrict__ e1w, const float* __restrict__ e1b,
                        const float* __restrict__ e2w, const float* __restrict__ e2b,
                        const float* __restrict__ d1w, const float* __restrict__ d1b,
                        const float* __restrict__ d2w, const float* __restrict__ d2b,
                        const float* __restrict__ d3w, const float* __restrict__ d3b,
                        const float* __restrict__ d4w, const float* __restrict__ d4b,
                        float* __restrict__ out)
{
    __shared__ float W[WTOT];
    // cat rows 0-1: dc3 (written by dec3); rows 2-13: jcat. cols 0,16 = zero pad.
    __shared__ float cat[14][17];
    __shared__ float fm1[6][14];    // col 13 pad (never read)
    __shared__ float embin2[2];     // psi, obsd_last

    const int t = threadIdx.x;

    // ===================== phase 0: one independent load wave ===============
    // x -> jcat (one element per thread)
    if (t < 180) {
        int c = t / 15, l = t % 15;
        float v;
        if (c < 6) {
            int j = c * 15 + l;
            v = (j < 2) ? 0.0f : x[7 + j - 2];
        } else {
            int j = (c - 6) * 15 + l;
            v = (j < 2) ? 0.0f : x[101 + j - 2];
        }
        cat[2 + c][1 + l] = v;
    }
    // zero pad columns of cat (28 writes)
    if (t >= 180 && t < 208) {
        int r = (t - 180) >> 1, c = (t & 1) ? 16 : 0;
        cat[r][c] = 0.0f;
    }
    // psi + obsd tail
    if (t == 220) {
        float qw = x[3], qx = x[4], qy = x[5], qz = x[6];
        embin2[0] = fatan2(qz, qw) - fatan2(-qx, qy);
        embin2[1] = x[100];
    }

    // conv1 weights -> regs on warps 1-3 (threads 32..109)
    float w1[36], b1 = 0.0f;
    int o1 = 0, l1 = 0;
    const bool is_c1 = (t >= 32 && t < 110);
    if (is_c1) {
        int u = t - 32;
        o1 = u / 13; l1 = u % 13;
        #pragma unroll
        for (int i = 0; i < 36; i++) w1[i] = c1w[o1 * 36 + i];
        b1 = c1b[o1];
    }
    // dec4 weights -> regs on warps 4-6 (threads 128..215)
    float w4[42], b4 = 0.0f;
    int o4 = 0, l4 = 0;
    const bool is_d4 = (t >= 128 && t < 216);
    if (is_d4) {
        int g = (t - 128) + 2; o4 = g / 15; l4 = g % 15;
        #pragma unroll
        for (int i = 0; i < 14; i++)
            #pragma unroll
            for (int h = 0; h < 3; h++)
                w4[i * 3 + h] = d4w[i * 18 + o4 * 3 + h];
        b4 = d4b[o4];
    }
    // warp-0 per-lane middle weights (preselected / zero-masked)
    float wc2[19];          // conv2 (lanes 0..11)
    if (t < 12) {
        int o = t / 3;
        #pragma unroll
        for (int k = 0; k < 18; k++) wc2[k] = c2w[o * 18 + k];
        wc2[18] = c2b[o];
    }
    float wd2[13];          // dec2 (lanes 0..9)
    if (t < 10) {
        int o = t / 5, l = t % 5;
        #pragma unroll
        for (int i = 0; i < 4; i++)
            #pragma unroll
            for (int p = 0; p < 3; p++) {
                int h = l - p;
                wd2[i * 3 + p] = (h >= 0 && h < 3) ? d2w[(i * 2 + o) * 3 + h] : 0.0f;
            }
        wd2[12] = d2b[o];
    }
    float wd3[7];           // dec3 (lanes 0..29)
    if (t < 30) {
        int o = t / 15, l = t % 15;
        #pragma unroll
        for (int i = 0; i < 2; i++)
            #pragma unroll
            for (int h = 0; h < 3; h++) {
                int p = l - h;
                wd3[i * 3 + h] = (p >= 0 && p < 13) ? d3w[(i * 2 + o) * 3 + h] : 0.0f;
            }
        wd3[6] = d3b[o];
    }
    // shared bank for remaining tiny stages (spread over all threads)
    #define CP(off, src, n) for (int i = t; i < (n); i += NT) W[(off) + i] = (src)[i];
    CP(C3W, c3w, 48)  CP(C3B, c3b, 4)
    CP(E1W, e1w, 24)  CP(E1B, e1b, 4)
    CP(E2W, e2w, 16)  CP(E2B, e2b, 4)
    CP(D1W, d1w, 48)  CP(D1B, d1b, 4)
    #undef CP
    __syncthreads();   // ---- b1: jcat + weights ready ----

    // ========== conv1 (warps 1-3)  ||  dec4 jcat-partial (warps 4-6) ========
    float partial = 0.0f;
    if (is_c1) {
        float s0 = b1, s1 = 0.0f, s2 = 0.0f;
        #pragma unroll
        for (int i = 0; i < 12; i++) {
            s0 = fmaf(w1[i * 3 + 0], cat[2 + i][1 + l1 + 0], s0);
            s1 = fmaf(w1[i * 3 + 1], cat[2 + i][1 + l1 + 1], s1);
            s2 = fmaf(w1[i * 3 + 2], cat[2 + i][1 + l1 + 2], s2);
        }
        fm1[o1][l1] = htanh(s0 + s1 + s2);
    } else if (is_d4) {
        float s0 = b4, s1 = 0.0f, s2 = 0.0f;
        #pragma unroll
        for (int h = 0; h < 3; h++) {
            int p = l4 - h + 2;   // [0..16], pads zero
            #pragma unroll
            for (int i = 2; i < 14; i++) {
                float v = cat[i][p];
                if (i % 3 == 0)      s0 = fmaf(w4[i * 3 + h], v, s0);
                else if (i % 3 == 1) s1 = fmaf(w4[i * 3 + h], v, s1);
                else                 s2 = fmaf(w4[i * 3 + h], v, s2);
            }
        }
        partial = s0 + s1 + s2;
    }
    __syncthreads();   // ---- b2: fm1 ready ----

    // ========== middle: warp 0, register-resident, shuffle-chained ==========
    if (t < 32) {
        const unsigned FULL = 0xffffffffu;

        // pool 13 -> 5 (lanes 0..29: o*5+p)
        int rr = (t < 30) ? t : 0;
        int po = rr / 5, pp = rr % 5;
        int S = (pp * 13) / 5;
        int sz4 = (((pp + 1) * 13 + 4) / 5 - S) == 4;
        float v3 = fm1[po][S + 3];
        float vp = fm1[po][S] + fm1[po][S + 1] + fm1[po][S + 2] + (sz4 ? v3 : 0.0f);
        vp *= sz4 ? 0.25f : (1.0f / 3.0f);

        // conv2 (lanes 0..11)
        int r2 = (t < 12) ? t : 0;
        int l2 = r2 % 3;
        float a0 = wc2[18], a1 = 0.0f;
        #pragma unroll
        for (int i = 0; i < 6; i++) {
            float v0 = __shfl_sync(FULL, vp, i * 5 + l2 + 0);
            float v1 = __shfl_sync(FULL, vp, i * 5 + l2 + 1);
            float v2 = __shfl_sync(FULL, vp, i * 5 + l2 + 2);
            a0 = fmaf(wc2[i * 3 + 0], v0, a0);
            a1 = fmaf(wc2[i * 3 + 1], v1, a1);
            a0 = fmaf(wc2[i * 3 + 2], v2, a0);
        }
        float fm2v = htanh(a0 + a1);

        // conv3 (lanes 0..3)
        int oc = t & 3;
        float c0 = W[C3B + oc], c1 = 0.0f;
        #pragma unroll
        for (int i = 0; i < 4; i++)
            #pragma unroll
            for (int h = 0; h < 3; h++) {
                float v = __shfl_sync(FULL, fm2v, i * 3 + h);
                float w = W[C3W + (oc * 4 + i) * 3 + h];
                if (h & 1) c1 = fmaf(w, v, c1); else c0 = fmaf(w, v, c0);
            }
        float c3v = htanh(c0 + c1);

        // emb1 (lanes 0..3, 6->4)
        float e0 = W[E1B + oc], e1a = 0.0f;
        #pragma unroll
        for (int i = 0; i < 4; i++) {
            float v = __shfl_sync(FULL, c3v, i);
            if (i & 1) e1a = fmaf(W[E1W + oc * 6 + i], v, e1a);
            else       e0  = fmaf(W[E1W + oc * 6 + i], v, e0);
        }
        e0  = fmaf(W[E1W + oc * 6 + 4], embin2[0], e0);
        e1a = fmaf(W[E1W + oc * 6 + 5], embin2[1], e1a);
        float e1v = htanh(e0 + e1a);

        // emb2 (lanes 0..3, 4->4)
        float f0 = W[E2B + oc], f1 = 0.0f;
        #pragma unroll
        for (int i = 0; i < 4; i++) {
            float v = __shfl_sync(FULL, e1v, i);
            if (i & 1) f1 = fmaf(W[E2W + oc * 4 + i], v, f1);
            else       f0 = fmaf(W[E2W + oc * 4 + i], v, f0);
        }
        float e2v = htanh(f0 + f1);

        // dec1 (lanes 0..11)
        int rd = (t < 12) ? t : 0;
        int od = rd / 3, ld = rd % 3;
        float g0 = W[D1B + od], g1 = 0.0f;
        #pragma unroll
        for (int i = 0; i < 4; i++) {
            float v = __shfl_sync(FULL, e2v, i);
            float w = W[D1W + (i * 4 + od) * 3 + ld];
            if (i & 1) g1 = fmaf(w, v, g1); else g0 = fmaf(w, v, g0);
        }
        float d1v = htanh(g0 + g1);

        // dec2 (lanes 0..9)
        float h0 = wd2[12], h1 = 0.0f;
        #pragma unroll
        for (int i = 0; i < 4; i++)
            #pragma unroll
            for (int p = 0; p < 3; p++) {
                float v = __shfl_sync(FULL, d1v, i * 3 + p);
                if (p & 1) h1 = fmaf(wd2[i * 3 + p], v, h1);
                else       h0 = fmaf(wd2[i * 3 + p], v, h0);
            }
        float d2v = htanh(h0 + h1);

        // dec3 + fused upsample (lanes 0..29) -> cat rows 0,1
        int r3 = (t < 30) ? t : 0;
        int o3 = r3 / 15, l3 = r3 % 15;
        float k0 = wd3[6], k1 = 0.0f;
        #pragma unroll
        for (int i = 0; i < 2; i++)
            #pragma unroll
            for (int h = 0; h < 3; h++) {
                int p = l3 - h;
                int pc = p < 0 ? 0 : (p > 12 ? 12 : p);
                int q = (pc * 5) / 13;                 // UP_IDX
                float v = __shfl_sync(FULL, d2v, i * 5 + q);
                if (h & 1) k1 = fmaf(wd3[i * 3 + h], v, k1);
                else       k0 = fmaf(wd3[i * 3 + h], v, k0);
            }
        if (t < 30) cat[o3][1 + l3] = htanh(k0 + k1);
    }
    __syncthreads();   // ---- b3: dc3 ready ----

    // ========== dec4 finish: dc3 rows only (6 FMA) then store ===============
    if (is_d4) {
        float s = partial;
        #pragma unroll
        for (int h = 0; h < 3; h++) {
            int p = l4 - h + 2;
            s = fmaf(w4[0 * 3 + h], cat[0][p], s);
            s = fmaf(w4[1 * 3 + h], cat[1][p], s);
        }
        out[t - 128] = s;
    }
}

extern "C" void kernel_launch(void* const* d_in, const int* in_sizes, int n_in,
                              void* d_out, int out_size) {
    (void)in_sizes; (void)n_in; (void)out_size;
    conv_policy_kernel<<<1, NT>>>(
        (const float*)d_in[0],
        (const float*)d_in[1],  (const float*)d_in[2],
        (const float*)d_in[3],  (const float*)d_in[4],
        (const float*)d_in[5],  (const float*)d_in[6],
        (const float*)d_in[7],  (const float*)d_in[8],
        (const float*)d_in[9],  (const float*)d_in[10],
        (const float*)d_in[11], (const float*)d_in[12],
        (const float*)d_in[13], (const float*)d_in[14],
        (const float*)d_in[15], (const float*)d_in[16],
        (const float*)d_in[17], (const float*)d_in[18],
        (float*)d_out);
}

// round 7
// speedup vs baseline: 1.3214x; 1.0561x over previous
#include <cuda_runtime.h>
#include <math.h>

#define NT 224

// shared weight bank for tiny middle stages
#define C3W 0
#define C3B 48
#define E1W 52
#define E1B 76
#define E2W 80
#define E2B 96
#define D1W 100
#define D1B 148
#define WTOT 152

#define NBAR(id, cnt) asm volatile("bar.sync %0, %1;" :: "r"(id), "r"(cnt) : "memory")

__device__ __forceinline__ float htanh(float x) {
    float y;
    asm("tanh.approx.f32 %0, %1;" : "=f"(y) : "f"(x));
    return y;
}

// fast atan2, ~1e-6 abs err (quaternion components, no 0/0 case)
__device__ __forceinline__ float fatan2(float y, float x) {
    float ax = fabsf(x), ay = fabsf(y);
    float mn = fminf(ax, ay), mx = fmaxf(ax, ay);
    float z = __fdividef(mn, mx);
    float z2 = z * z;
    float p = -0.0117212f;
    p = fmaf(p, z2,  0.05265332f);
    p = fmaf(p, z2, -0.11643287f);
    p = fmaf(p, z2,  0.19354346f);
    p = fmaf(p, z2, -0.33262347f);
    p = fmaf(p, z2,  0.99997726f);
    float a = p * z;
    if (ay > ax) a = 1.57079632679f - a;
    if (x < 0.0f) a = 3.14159265359f - a;
    return copysignf(a, y);
}

__global__ __launch_bounds__(NT, 1)
void conv_policy_kernel(const float* __restrict__ x,
                        const float* __restrict__ c1w, const float* __restrict__ c1b,
                        const float* __restrict__ c2w, const float* __restrict__ c2b,
                        const float* __restrict__ c3w, const float* __restrict__ c3b,
                        const float* __restrict__ e1w, const float* __restrict__ e1b,
                        const float* __restrict__ e2w, const float* __restrict__ e2b,
                        const float* __restrict__ d1w, const float* __restrict__ d1b,
                        const float* __restrict__ d2w, const float* __restrict__ d2b,
                        const float* __restrict__ d3w, const float* __restrict__ d3b,
                        const float* __restrict__ d4w, const float* __restrict__ d4b,
                        float* __restrict__ out)
{
    __shared__ float W[WTOT];
    // cat rows 0-1: dc3 (written by dec3); rows 2-13: jcat. cols 0,16 = zero pad.
    __shared__ float cat[14][17];
    __shared__ float fm1[6][14];    // col 13 pad (never read)
    __shared__ float embin2[2];     // psi, obsd_last

    const int t = threadIdx.x;

    // ===================== phase 0: one independent load wave ===============
    if (t < 180) {
        int c = t / 15, l = t % 15;
        float v;
        if (c < 6) {
            int j = c * 15 + l;
            v = (j < 2) ? 0.0f : x[7 + j - 2];
        } else {
            int j = (c - 6) * 15 + l;
            v = (j < 2) ? 0.0f : x[101 + j - 2];
        }
        cat[2 + c][1 + l] = v;
    }
    if (t >= 180 && t < 208) {
        int r = (t - 180) >> 1, c = (t & 1) ? 16 : 0;
        cat[r][c] = 0.0f;
    }
    if (t == 220) {
        float qw = x[3], qx = x[4], qy = x[5], qz = x[6];
        embin2[0] = fatan2(qz, qw) - fatan2(-qx, qy);
        embin2[1] = x[100];
    }

    // conv1 weights -> regs on warps 1-3 (threads 32..109)
    float w1[36], b1 = 0.0f;
    int o1 = 0, l1 = 0;
    const bool is_c1 = (t >= 32 && t < 110);
    if (is_c1) {
        int u = t - 32;
        o1 = u / 13; l1 = u % 13;
        #pragma unroll
        for (int i = 0; i < 36; i++) w1[i] = c1w[o1 * 36 + i];
        b1 = c1b[o1];
    }
    // dec4 weights -> regs on warps 4-6 (threads 128..215)
    float w4[42], b4 = 0.0f;
    int o4 = 0, l4 = 0;
    const bool is_d4 = (t >= 128 && t < 216);
    if (is_d4) {
        int g = (t - 128) + 2; o4 = g / 15; l4 = g % 15;
        #pragma unroll
        for (int i = 0; i < 14; i++)
            #pragma unroll
            for (int h = 0; h < 3; h++)
                w4[i * 3 + h] = d4w[i * 18 + o4 * 3 + h];
        b4 = d4b[o4];
    }
    // warp-0 per-lane middle weights (preselected / zero-masked)
    float wc2[19];          // conv2 (lanes 0..11)
    if (t < 12) {
        int o = t / 3;
        #pragma unroll
        for (int k = 0; k < 18; k++) wc2[k] = c2w[o * 18 + k];
        wc2[18] = c2b[o];
    }
    float wd2[13];          // dec2 (lanes 0..9)
    if (t < 10) {
        int o = t / 5, l = t % 5;
        #pragma unroll
        for (int i = 0; i < 4; i++)
            #pragma unroll
            for (int p = 0; p < 3; p++) {
                int h = l - p;
                wd2[i * 3 + p] = (h >= 0 && h < 3) ? d2w[(i * 2 + o) * 3 + h] : 0.0f;
            }
        wd2[12] = d2b[o];
    }
    float wd3[7];           // dec3 (lanes 0..29)
    if (t < 30) {
        int o = t / 15, l = t % 15;
        #pragma unroll
        for (int i = 0; i < 2; i++)
            #pragma unroll
            for (int h = 0; h < 3; h++) {
                int p = l - h;
                wd3[i * 3 + h] = (p >= 0 && p < 13) ? d3w[(i * 2 + o) * 3 + h] : 0.0f;
            }
        wd3[6] = d3b[o];
    }
    // shared bank for remaining tiny stages (loaded by warps 1-6 only)
    if (t >= 32) {
        int u = t - 32;  // 0..191
        #define CP(off, src, n) for (int i = u; i < (n); i += 192) W[(off) + i] = (src)[i];
        CP(C3W, c3w, 48)  CP(C3B, c3b, 4)
        CP(E1W, e1w, 24)  CP(E1B, e1b, 4)
        CP(E2W, e2w, 16)  CP(E2B, e2b, 4)
        CP(D1W, d1w, 48)  CP(D1B, d1b, 4)
        #undef CP
    }
    __syncthreads();   // ---- b1: jcat + weights + W bank ready ----

    if (t < 32) {
        // ======== warp 0: prefetch middle weights (hidden under conv1) ======
        const int oc = t & 3;
        const int rd = (t < 12) ? t : 0;
        const int od = rd / 3, ld = rd % 3;
        float wc3[12], we1[6], we2[4], wd1[4];
        #pragma unroll
        for (int i = 0; i < 4; i++)
            #pragma unroll
            for (int h = 0; h < 3; h++)
                wc3[i * 3 + h] = W[C3W + (oc * 4 + i) * 3 + h];
        float bc3 = W[C3B + oc];
        #pragma unroll
        for (int i = 0; i < 6; i++) we1[i] = W[E1W + oc * 6 + i];
        float be1 = W[E1B + oc];
        #pragma unroll
        for (int i = 0; i < 4; i++) we2[i] = W[E2W + oc * 4 + i];
        float be2 = W[E2B + oc];
        #pragma unroll
        for (int i = 0; i < 4; i++) wd1[i] = W[D1W + (i * 4 + od) * 3 + ld];
        float bd1 = W[D1B + od];

        NBAR(1, 128);   // ---- fm1 ready (warps 0-3) ----

        // ======== middle: register-resident, shuffle-chained, no mem ops ====
        const unsigned FULL = 0xffffffffu;

        // pool 13 -> 5 (lanes 0..29: o*5+p)
        int rr = (t < 30) ? t : 0;
        int po = rr / 5, pp = rr % 5;
        int S = (pp * 13) / 5;
        int sz4 = (((pp + 1) * 13 + 4) / 5 - S) == 4;
        float v3 = fm1[po][S + 3];
        float vp = fm1[po][S] + fm1[po][S + 1] + fm1[po][S + 2] + (sz4 ? v3 : 0.0f);
        vp *= sz4 ? 0.25f : (1.0f / 3.0f);

        // conv2 (lanes 0..11)
        int r2 = (t < 12) ? t : 0;
        int l2 = r2 % 3;
        float a0 = wc2[18], a1 = 0.0f;
        #pragma unroll
        for (int i = 0; i < 6; i++) {
            float v0 = __shfl_sync(FULL, vp, i * 5 + l2 + 0);
            float v1 = __shfl_sync(FULL, vp, i * 5 + l2 + 1);
            float v2 = __shfl_sync(FULL, vp, i * 5 + l2 + 2);
            a0 = fmaf(wc2[i * 3 + 0], v0, a0);
            a1 = fmaf(wc2[i * 3 + 1], v1, a1);
            a0 = fmaf(wc2[i * 3 + 2], v2, a0);
        }
        float fm2v = htanh(a0 + a1);

        // conv3 (lanes 0..3)
        float c0 = bc3, c1 = 0.0f;
        #pragma unroll
        for (int i = 0; i < 4; i++)
            #pragma unroll
            for (int h = 0; h < 3; h++) {
                float v = __shfl_sync(FULL, fm2v, i * 3 + h);
                if (h & 1) c1 = fmaf(wc3[i * 3 + h], v, c1);
                else       c0 = fmaf(wc3[i * 3 + h], v, c0);
            }
        float c3v = htanh(c0 + c1);

        // emb1 (lanes 0..3, 6->4)
        float e0 = be1, e1a = 0.0f;
        #pragma unroll
        for (int i = 0; i < 4; i++) {
            float v = __shfl_sync(FULL, c3v, i);
            if (i & 1) e1a = fmaf(we1[i], v, e1a);
            else       e0  = fmaf(we1[i], v, e0);
        }
        e0  = fmaf(we1[4], embin2[0], e0);
        e1a = fmaf(we1[5], embin2[1], e1a);
        float e1v = htanh(e0 + e1a);

        // emb2 (lanes 0..3, 4->4)
        float f0 = be2, f1 = 0.0f;
        #pragma unroll
        for (int i = 0; i < 4; i++) {
            float v = __shfl_sync(FULL, e1v, i);
            if (i & 1) f1 = fmaf(we2[i], v, f1);
            else       f0 = fmaf(we2[i], v, f0);
        }
        float e2v = htanh(f0 + f1);

        // dec1 (lanes 0..11)
        float g0 = bd1, g1 = 0.0f;
        #pragma unroll
        for (int i = 0; i < 4; i++) {
            float v = __shfl_sync(FULL, e2v, i);
            if (i & 1) g1 = fmaf(wd1[i], v, g1);
            else       g0 = fmaf(wd1[i], v, g0);
        }
        float d1v = htanh(g0 + g1);

        // dec2 (lanes 0..9)
        float h0 = wd2[12], h1 = 0.0f;
        #pragma unroll
        for (int i = 0; i < 4; i++)
            #pragma unroll
            for (int p = 0; p < 3; p++) {
                float v = __shfl_sync(FULL, d1v, i * 3 + p);
                if (p & 1) h1 = fmaf(wd2[i * 3 + p], v, h1);
                else       h0 = fmaf(wd2[i * 3 + p], v, h0);
            }
        float d2v = htanh(h0 + h1);

        // dec3 + fused upsample (lanes 0..29) -> cat rows 0,1
        int r3 = (t < 30) ? t : 0;
        int o3 = r3 / 15, l3 = r3 % 15;
        float k0 = wd3[6], k1 = 0.0f;
        #pragma unroll
        for (int i = 0; i < 2; i++)
            #pragma unroll
            for (int h = 0; h < 3; h++) {
                int p = l3 - h;
                int pc = p < 0 ? 0 : (p > 12 ? 12 : p);
                int q = (pc * 5) / 13;                 // UP_IDX
                float v = __shfl_sync(FULL, d2v, i * 5 + q);
                if (h & 1) k1 = fmaf(wd3[i * 3 + h], v, k1);
                else       k0 = fmaf(wd3[i * 3 + h], v, k0);
            }
        if (t < 30) cat[o3][1 + l3] = htanh(k0 + k1);

        NBAR(2, 128);   // ---- dc3 ready (warp 0 + warps 4-6) ----
    } else if (t < 128) {
        // ======== warps 1-3: conv1 (12,15) k=3 -> (6,13), tanh ==============
        if (is_c1) {
            float s0 = b1, s1 = 0.0f, s2 = 0.0f;
            #pragma unroll
            for (int i = 0; i < 12; i++) {
                s0 = fmaf(w1[i * 3 + 0], cat[2 + i][1 + l1 + 0], s0);
                s1 = fmaf(w1[i * 3 + 1], cat[2 + i][1 + l1 + 1], s1);
                s2 = fmaf(w1[i * 3 + 2], cat[2 + i][1 + l1 + 2], s2);
            }
            fm1[o1][l1] = htanh(s0 + s1 + s2);
        }
        NBAR(1, 128);   // fm1 ready
    } else {
        // ======== warps 4-6: dec4 jcat-partial, then wait for dc3 ===========
        float partial = 0.0f;
        if (is_d4) {
            float s0 = b4, s1 = 0.0f, s2 = 0.0f;
            #pragma unroll
            for (int h = 0; h < 3; h++) {
                int p = l4 - h + 2;   // [0..16], pads zero
                #pragma unroll
                for (int i = 2; i < 14; i++) {
                    float v = cat[i][p];
                    if (i % 3 == 0)      s0 = fmaf(w4[i * 3 + h], v, s0);
                    else if (i % 3 == 1) s1 = fmaf(w4[i * 3 + h], v, s1);
                    else                 s2 = fmaf(w4[i * 3 + h], v, s2);
                }
            }
            partial = s0 + s1 + s2;
        }
        NBAR(2, 128);   // dc3 ready

        if (is_d4) {
            float s = partial;
            #pragma unroll
            for (int h = 0; h < 3; h++) {
                int p = l4 - h + 2;
                s = fmaf(w4[0 * 3 + h], cat[0][p], s);
                s = fmaf(w4[1 * 3 + h], cat[1][p], s);
            }
            out[t - 128] = s;
        }
    }
}

extern "C" void kernel_launch(void* const* d_in, const int* in_sizes, int n_in,
                              void* d_out, int out_size) {
    (void)in_sizes; (void)n_in; (void)out_size;
    conv_policy_kernel<<<1, NT>>>(
        (const float*)d_in[0],
        (const float*)d_in[1],  (const float*)d_in[2],
        (const float*)d_in[3],  (const float*)d_in[4],
        (const float*)d_in[5],  (const float*)d_in[6],
        (const float*)d_in[7],  (const float*)d_in[8],
        (const float*)d_in[9],  (const float*)d_in[10],
        (const float*)d_in[11], (const float*)d_in[12],
        (const float*)d_in[13], (const float*)d_in[14],
        (const float*)d_in[15], (const float*)d_in[16],
        (const float*)d_in[17], (const float*)d_in[18],
        (float*)d_out);
}